// round 15
// baseline (speedup 1.0000x reference)
#include <cuda_runtime.h>

// SimpleSNN: T=500 sequential steps, B=2048, 12 -> 38 (RLeaky) -> 7 (Leaky)
// Outputs flat: spk1[T,B,38], mem1[T,B,38], spk2[T,B,7], mem2[T,B,7]
//
// Round-batched pipeline, G=50 steps per __syncthreads (11 barriers total).
// x staged one round ahead via cp.async.cg 16B (uniform: all 192 threads
// issue and wait; full-round overlap). Ballot-bitmask spk1, imm-offset
// stores. FP op order bit-identical to all passing rounds.

#define T_STEPS  500
#define BATCH    2048
#define NIN      12
#define NL1      38
#define NL2      7
#define NB       4              // batch elements per block
#define NTHREADS 192
#define PROD_T   160            // warps 0-4 run the L1 step body (ballot)
#define L1_T     (NB*NL1)       // 152 real L1 threads
#define L2_BASE  160            // L2 warp
#define L2_T     (NB*NL2)       // 28
#define X_T      (NB*NIN)       // 48 x floats per step (192 B, contiguous)
#define W2STRIDE 44             // padded W2 row stride
#define G        50             // steps per round (500 = 10 rounds)
#define NSLOT    (2*G)          // ring depth (2 rounds)
#define STEP1    (BATCH*NL1)    // element stride between steps, layer-1 outputs
#define STEP2    (BATCH*NL2)    // element stride between steps, layer-2 outputs
#define XCP      (G*12)         // 16B cp.async ops per round (12 per step)

#define CPA16(dst, src) asm volatile("cp.async.cg.shared.global [%0], [%1], 16;" \
                                     :: "r"(dst), "l"(src) : "memory")
#define CPCOMMIT()      asm volatile("cp.async.commit_group;" ::: "memory")
#define CPWAIT0()       asm volatile("cp.async.wait_group 0;" ::: "memory")

__global__ __launch_bounds__(NTHREADS, 4)
void snn_scan_kernel(const float* __restrict__ x,
                     const float* __restrict__ W1,
                     const float* __restrict__ V,
                     const float* __restrict__ W2,
                     const float* __restrict__ pb1,
                     const float* __restrict__ pb2,
                     const float* __restrict__ pth,
                     float* __restrict__ out)
{
    __shared__ float    xsh[NSLOT][X_T];   // x ring: one 192B slot per step
    __shared__ unsigned sbit[NSLOT][8];    // spike bitmask ring: 5 words/slot
    __shared__ float    w2sh[NL2 * W2STRIDE];

    const int tid  = threadIdx.x;
    const int wid  = tid >> 5;
    const int b0   = blockIdx.x * NB;
    const float thr = *pth;

    const size_t stepx = (size_t)BATCH * NIN;
    const float* xblk  = x + (size_t)b0 * NIN;   // this block's x column base
    const unsigned xsh0 = (unsigned)__cvta_generic_to_shared(&xsh[0][0]);

    // ---- one-time shared init ----
    for (int i = tid; i < NL2 * W2STRIDE; i += NTHREADS) {
        int k = i / W2STRIDE;
        int j = i - k * W2STRIDE;
        w2sh[i] = (j < NL1) ? W2[k * NL1 + j] : 0.0f;
    }

    const bool isP  = (tid < PROD_T);    // runs L1 step body (incl. ballot)
    const bool isL1 = (tid < L1_T);      // real L1 neuron
    const bool isL2 = (tid >= L2_BASE) && (tid < L2_BASE + L2_T);

    // ---- layer 1 per-thread state ----
    const float beta1 = *pb1;
    float w1r[NIN];
    float vj = 0.f, mem1 = 0.f, spk1 = 0.f;
    int xoff = 0;
    float *pS1 = out, *pM1 = out;
    if (isL1) {
        int bl = tid / NL1, j = tid - bl * NL1;
        #pragma unroll
        for (int i = 0; i < NIN; ++i) w1r[i] = W1[j * NIN + i];
        vj   = V[j];
        xoff = bl * NIN;
        size_t o = (size_t)(b0 + bl) * NL1 + j;
        pS1 = out + o;
        pM1 = out + (size_t)T_STEPS * BATCH * NL1 + o;
    } else {
        #pragma unroll
        for (int i = 0; i < NIN; ++i) w1r[i] = 0.f;  // ballast lanes: defined math
    }

    // ---- layer 2 per-thread state ----
    const float beta2 = *pb2;
    float mem2 = 0.f;
    int w0i = 0, offi = 0;
    const float4* w2v = (const float4*)w2sh;
    float *pS2 = out, *pM2 = out;
    if (isL2) {
        int t2 = tid - L2_BASE;
        int bl = t2 / NL2, k = t2 - bl * NL2;
        int base = bl * NL1;               // bit index of (bl, j=0)
        w0i  = base >> 5;                  // 0..3
        offi = base & 31;
        w2v  = (const float4*)&w2sh[k * W2STRIDE];
        size_t o = (size_t)(b0 + bl) * NL2 + k;
        pS2 = out + (size_t)2 * T_STEPS * BATCH * NL1 + o;
        pM2 = pS2 + (size_t)T_STEPS * BATCH * NL2;
    }

    // ---- x round-copy: all 192 threads, ~3 x 16B cp.async each ----
    // op i -> step i/12 of the round, 16B chunk i%12.
#define XSTAGE(HALF, T0)                                                       \
        {                                                                      \
            _Pragma("unroll")                                                  \
            for (int i = tid; i < XCP; i += NTHREADS) {                        \
                int st_ = i / 12, ch_ = i % 12;                                \
                unsigned d_ = xsh0 + (unsigned)(((HALF) + st_) * (X_T * 4)     \
                                                + ch_ * 16);                   \
                const float* s_ = xblk + (size_t)((T0) + st_) * stepx + ch_*4; \
                CPA16(d_, s_);                                                 \
            }                                                                  \
            CPCOMMIT();                                                        \
        }

    // prologue: synchronously stage round 0 (steps 0-49) into half 0
    XSTAGE(0, 0)
    CPWAIT0();
    int tpre = G;   // step-base of the round to stage at the next round-top
    __syncthreads();

    // one L1 step from ring slot SLOT, in-round step index S (0..G-1).
    // Serial fmaf chain — EXACT passing order. Imm-offset stores.
#define L1STEP(SLOT, S)                                                        \
        {                                                                      \
            const float4* xv_ = (const float4*)&xsh[SLOT][xoff];               \
            float4 a = xv_[0], b = xv_[1], c = xv_[2];                         \
            float cur = a.x * w1r[0];                                          \
            cur = fmaf(a.y, w1r[1], cur);                                      \
            cur = fmaf(a.z, w1r[2], cur);                                      \
            cur = fmaf(a.w, w1r[3], cur);                                      \
            cur = fmaf(b.x, w1r[4], cur);                                      \
            cur = fmaf(b.y, w1r[5], cur);                                      \
            cur = fmaf(b.z, w1r[6], cur);                                      \
            cur = fmaf(b.w, w1r[7], cur);                                      \
            cur = fmaf(c.x, w1r[8], cur);                                      \
            cur = fmaf(c.y, w1r[9], cur);                                      \
            cur = fmaf(c.z, w1r[10], cur);                                     \
            cur = fmaf(c.w, w1r[11], cur);                                     \
            float mv_ = fmaf(beta1, mem1, cur);                                \
            mv_ = fmaf(vj, spk1, mv_);                                         \
            bool pr_ = (mv_ > thr);                                            \
            float spv_ = pr_ ? 1.0f : 0.0f;                                    \
            mv_ = fmaf(-spv_, thr, mv_);                                       \
            mem1 = mv_; spk1 = spv_;                                           \
            unsigned bb_ = __ballot_sync(0xFFFFFFFFu, isL1 && pr_);            \
            if ((tid & 31) == 0) sbit[SLOT][wid] = bb_;                        \
            if (isL1) {                                                        \
                pS1[(S) * STEP1] = spv_;                                       \
                pM1[(S) * STEP1] = mv_;                                        \
            }                                                                  \
        }

    // one L2 step: 2-word bitmask read + predicated adds (bit-exact vs fmaf).
#define L2STEP(SLOT, S)                                                        \
        {                                                                      \
            unsigned lo_ = sbit[SLOT][w0i];                                    \
            unsigned hi_ = sbit[SLOT][w0i + 1];                                \
            unsigned long long vb_ =                                           \
                ((((unsigned long long)hi_) << 32) | lo_) >> offi;             \
            vb_ &= 0x3FFFFFFFFFull;   /* keep bits 0..37 (pad = 0) */          \
            float acc0 = 0.0f, acc1 = 0.0f, acc2 = 0.0f, acc3 = 0.0f;          \
            _Pragma("unroll")                                                  \
            for (int q = 0; q < 10; ++q) {                                     \
                float4 w4 = w2v[q];                                            \
                acc0 = ((vb_ >> (4 * q + 0)) & 1) ? acc0 + w4.x : acc0;        \
                acc1 = ((vb_ >> (4 * q + 1)) & 1) ? acc1 + w4.y : acc1;        \
                acc2 = ((vb_ >> (4 * q + 2)) & 1) ? acc2 + w4.z : acc2;        \
                acc3 = ((vb_ >> (4 * q + 3)) & 1) ? acc3 + w4.w : acc3;        \
            }                                                                  \
            float cur2 = (acc0 + acc1) + (acc2 + acc3);                        \
            float m2_ = fmaf(beta2, mem2, cur2);                               \
            float s2_ = (m2_ > thr) ? 1.0f : 0.0f;                             \
            m2_ = fmaf(-s2_, thr, m2_);                                        \
            mem2 = m2_;                                                        \
            pS2[(S) * STEP2] = s2_;                                            \
            pM2[(S) * STEP2] = m2_;                                            \
        }

    // L1 round at ring half BASE (0 or G):
    //   top   : all threads issue next round's cp.async into half BASE^G
    //   middle: producers run G L1 steps off half BASE
    //   bottom: all threads drain the async group (issued a full round ago
    //           for the PREVIOUS stage -> effectively free)
#define L1ROUND(BASE)                                                          \
        {                                                                      \
            if (tpre < T_STEPS) XSTAGE((BASE) ^ G, tpre)                       \
            else                CPCOMMIT();                                    \
            tpre += G;                                                         \
            if (isP) {                                                         \
                _Pragma("unroll")                                              \
                for (int ls = 0; ls < G; ++ls)                                 \
                    L1STEP((BASE) + ls, ls)                                    \
                if (isL1) { pS1 += G * STEP1; pM1 += G * STEP1; }              \
            }                                                                  \
            CPWAIT0();                                                         \
        }

#define L2ROUND(BASE)                                                          \
        if (isL2) {                                                            \
            _Pragma("unroll")                                                  \
            for (int ks = 0; ks < G; ++ks)                                     \
                L2STEP((BASE) + ks, ks)                                        \
            pS2 += G * STEP2; pM2 += G * STEP2;                                \
        }

    // round 0: L1 only (computes steps 0-49 off half 0; stages 50-99)
    L1ROUND(0)
    __syncthreads();

    // rounds 1..8: L1 leads, L2 trails one round (4 pairs)
    #pragma unroll 1
    for (int r = 0; r < 4; ++r) {
        L1ROUND(G) L2ROUND(0)
        __syncthreads();
        L1ROUND(0) L2ROUND(G)
        __syncthreads();
    }

    // round 9: L1 steps 450-499 (half G), L2 steps 400-449 (half 0)
    L1ROUND(G) L2ROUND(0)
    __syncthreads();

    // epilogue: L2 steps 450-499 (half G)
    L2ROUND(G)

#undef L1STEP
#undef L2STEP
#undef L1ROUND
#undef L2ROUND
#undef XSTAGE
}

extern "C" void kernel_launch(void* const* d_in, const int* in_sizes, int n_in,
                              void* d_out, int out_size)
{
    const float* x   = (const float*)d_in[0];
    const float* W1  = (const float*)d_in[1];
    const float* V   = (const float*)d_in[2];
    const float* W2  = (const float*)d_in[3];
    const float* b1  = (const float*)d_in[4];
    const float* b2  = (const float*)d_in[5];
    const float* th  = (const float*)d_in[6];
    float* out = (float*)d_out;

    dim3 grid(BATCH / NB);   // 512 blocks; 4 blocks/SM -> single wave
    dim3 block(NTHREADS);
    snn_scan_kernel<<<grid, block>>>(x, W1, V, W2, b1, b2, th, out);
}

// round 16
// speedup vs baseline: 2.0932x; 2.0932x over previous
#include <cuda_runtime.h>

// SimpleSNN: T=500 sequential steps, B=2048, 12 -> 38 (RLeaky) -> 7 (Leaky)
// Outputs flat: spk1[T,B,38], mem1[T,B,38], spk2[T,B,7], mem2[T,B,7]
//
// Round-batched pipeline, G=25 steps per __syncthreads (21 barriers total).
// SINGLE-EXPANSION round loop (runtime ring-half index) -> ~4x smaller code
// than the unrolled two-phase version (I$-safe). Register x staging over 96
// stager threads (13/12 steps each, no cp.async). Ballot-bitmask spk1,
// imm-offset stores. FP op order bit-identical to all passing rounds.

#define T_STEPS  500
#define BATCH    2048
#define NIN      12
#define NL1      38
#define NL2      7
#define NB       4              // batch elements per block
#define NTHREADS 192
#define PROD_T   160            // warps 0-4 run the L1 step body (ballot)
#define L1_T     (NB*NL1)       // 152 real L1 threads
#define L2_BASE  160            // L2 warp
#define L2_T     (NB*NL2)       // 28
#define X_T      (NB*NIN)       // 48 x floats per step
#define STAGE_T  96             // stager threads (2 groups of 48)
#define W2STRIDE 44             // padded W2 row stride
#define G        25             // steps per round (500 = 20 rounds)
#define NSLOT    (2*G)          // ring depth (2 rounds)
#define NROUND   (T_STEPS/G)    // 20
#define STEP1    (BATCH*NL1)    // element stride between steps, layer-1 outputs
#define STEP2    (BATCH*NL2)    // element stride between steps, layer-2 outputs

__global__ __launch_bounds__(NTHREADS, 4)
void snn_scan_kernel(const float* __restrict__ x,
                     const float* __restrict__ W1,
                     const float* __restrict__ V,
                     const float* __restrict__ W2,
                     const float* __restrict__ pb1,
                     const float* __restrict__ pb2,
                     const float* __restrict__ pth,
                     float* __restrict__ out)
{
    __shared__ float    xsh[NSLOT][X_T];   // x ring: one slot per step
    __shared__ unsigned sbit[NSLOT][8];    // spike bitmask ring: 5 words/slot
    __shared__ float    w2sh[NL2 * W2STRIDE];

    const int tid  = threadIdx.x;
    const int wid  = tid >> 5;
    const int b0   = blockIdx.x * NB;
    const float thr = *pth;

    const size_t stepx = (size_t)BATCH * NIN;
    const float* xblk  = x + (size_t)b0 * NIN;   // x[t][b0..b0+3][0..11] contiguous 48

    // ---- one-time shared init ----
    for (int i = tid; i < NL2 * W2STRIDE; i += NTHREADS) {
        int k = i / W2STRIDE;
        int j = i - k * W2STRIDE;
        w2sh[i] = (j < NL1) ? W2[k * NL1 + j] : 0.0f;
    }

    const bool isP  = (tid < PROD_T);    // runs L1 step body (incl. ballot)
    const bool isL1 = (tid < L1_T);      // real L1 neuron
    const bool isS  = (tid < STAGE_T);   // x stager (also an L1 thread)
    const bool isL2 = (tid >= L2_BASE) && (tid < L2_BASE + L2_T);

    // ---- layer 1 per-thread state ----
    const float beta1 = *pb1;
    float w1r[NIN];
    float vj = 0.f, mem1 = 0.f, spk1 = 0.f;
    int xoff = 0;
    float *pS1 = out, *pM1 = out;
    if (isL1) {
        int bl = tid / NL1, j = tid - bl * NL1;
        #pragma unroll
        for (int i = 0; i < NIN; ++i) w1r[i] = W1[j * NIN + i];
        vj   = V[j];
        xoff = bl * NIN;
        size_t o = (size_t)(b0 + bl) * NL1 + j;
        pS1 = out + o;
        pM1 = out + (size_t)T_STEPS * BATCH * NL1 + o;
    } else {
        #pragma unroll
        for (int i = 0; i < NIN; ++i) w1r[i] = 0.f;  // ballast lanes: defined math
    }

    // ---- layer 2 per-thread state ----
    const float beta2 = *pb2;
    float mem2 = 0.f;
    int w0i = 0, offi = 0;
    const float4* w2v = (const float4*)w2sh;
    float *pS2 = out, *pM2 = out;
    if (isL2) {
        int t2 = tid - L2_BASE;
        int bl = t2 / NL2, k = t2 - bl * NL2;
        int base = bl * NL1;               // bit index of (bl, j=0)
        w0i  = base >> 5;                  // 0..3
        offi = base & 31;
        w2v  = (const float4*)&w2sh[k * W2STRIDE];
        size_t o = (size_t)(b0 + bl) * NL2 + k;
        pS2 = out + (size_t)2 * T_STEPS * BATCH * NL1 + o;
        pM2 = pS2 + (size_t)T_STEPS * BATCH * NL2;
    }

    // ---- x staging: 96 stagers; group sg owns in-round steps soff..soff+hs-1
    // for its element su (0..47). Group 0: 13 steps, group 1: 12 steps. ----
    const int su   = tid % 48;
    const int sg   = tid / 48;             // 0 or 1 (for tid < 96)
    const int hs   = sg ? 12 : 13;         // steps held by this stager
    const int soff = sg ? 13 : 0;          // first in-round step of the group
    float xn[13];
    #pragma unroll
    for (int i = 0; i < 13; ++i) xn[i] = 0.f;
    const float* xq = x;
    if (isS) {
        // stage round 0 (steps 0..24) directly into slots
        #pragma unroll
        for (int i = 0; i < 13; ++i)
            if (i < hs)
                xsh[soff + i][su] = xblk[su + (size_t)(soff + i) * stepx];
        // hold round 1 (steps 25..49) in regs
        #pragma unroll
        for (int i = 0; i < 13; ++i)
            if (i < hs)
                xn[i] = xblk[su + (size_t)(G + soff + i) * stepx];
        xq = xblk + su + (size_t)(2 * G + soff) * stepx;
    }
    __syncthreads();

    // one L1 step from ring slot SLOT (runtime), in-round index S (0..G-1).
    // Serial fmaf chain — EXACT passing order. Imm-offset stores.
#define L1STEP(SLOT, S)                                                        \
        {                                                                      \
            const float4* xv_ = (const float4*)&xsh[SLOT][xoff];               \
            float4 a = xv_[0], b = xv_[1], c = xv_[2];                         \
            float cur = a.x * w1r[0];                                          \
            cur = fmaf(a.y, w1r[1], cur);                                      \
            cur = fmaf(a.z, w1r[2], cur);                                      \
            cur = fmaf(a.w, w1r[3], cur);                                      \
            cur = fmaf(b.x, w1r[4], cur);                                      \
            cur = fmaf(b.y, w1r[5], cur);                                      \
            cur = fmaf(b.z, w1r[6], cur);                                      \
            cur = fmaf(b.w, w1r[7], cur);                                      \
            cur = fmaf(c.x, w1r[8], cur);                                      \
            cur = fmaf(c.y, w1r[9], cur);                                      \
            cur = fmaf(c.z, w1r[10], cur);                                     \
            cur = fmaf(c.w, w1r[11], cur);                                     \
            float mv_ = fmaf(beta1, mem1, cur);                                \
            mv_ = fmaf(vj, spk1, mv_);                                         \
            bool pr_ = (mv_ > thr);                                            \
            float spv_ = pr_ ? 1.0f : 0.0f;                                    \
            mv_ = fmaf(-spv_, thr, mv_);                                       \
            mem1 = mv_; spk1 = spv_;                                           \
            unsigned bb_ = __ballot_sync(0xFFFFFFFFu, isL1 && pr_);            \
            if ((tid & 31) == 0) sbit[SLOT][wid] = bb_;                        \
            if (isL1) {                                                        \
                pS1[(S) * STEP1] = spv_;                                       \
                pM1[(S) * STEP1] = mv_;                                        \
            }                                                                  \
        }

    // one L2 step: 2-word bitmask read + predicated adds (bit-exact vs fmaf).
#define L2STEP(SLOT, S)                                                        \
        {                                                                      \
            unsigned lo_ = sbit[SLOT][w0i];                                    \
            unsigned hi_ = sbit[SLOT][w0i + 1];                                \
            unsigned long long vb_ =                                           \
                ((((unsigned long long)hi_) << 32) | lo_) >> offi;             \
            vb_ &= 0x3FFFFFFFFFull;   /* keep bits 0..37 (pad = 0) */          \
            float acc0 = 0.0f, acc1 = 0.0f, acc2 = 0.0f, acc3 = 0.0f;          \
            _Pragma("unroll")                                                  \
            for (int q = 0; q < 10; ++q) {                                     \
                float4 w4 = w2v[q];                                            \
                acc0 = ((vb_ >> (4 * q + 0)) & 1) ? acc0 + w4.x : acc0;        \
                acc1 = ((vb_ >> (4 * q + 1)) & 1) ? acc1 + w4.y : acc1;        \
                acc2 = ((vb_ >> (4 * q + 2)) & 1) ? acc2 + w4.z : acc2;        \
                acc3 = ((vb_ >> (4 * q + 3)) & 1) ? acc3 + w4.w : acc3;        \
            }                                                                  \
            float cur2 = (acc0 + acc1) + (acc2 + acc3);                        \
            float m2_ = fmaf(beta2, mem2, cur2);                               \
            float s2_ = (m2_ > thr) ? 1.0f : 0.0f;                             \
            m2_ = fmaf(-s2_, thr, m2_);                                        \
            mem2 = m2_;                                                        \
            pS2[(S) * STEP2] = s2_;                                            \
            pM2[(S) * STEP2] = m2_;                                            \
        }

    // ---- main loop: 20 rounds, ONE barrier each; bodies expanded ONCE ----
    // Round r: L1 computes round r at half `base`; stagers write round r+1
    // into half base^G and prefetch round r+2; L2 (r>0) consumes round r-1
    // at half base^G. All reuse pairs separated by one __syncthreads.
    int base = 0;
    int tpre = 2 * G;                      // step-base of next prefetch
    #pragma unroll 1
    for (int r = 0; r < NROUND; ++r) {
        if (isP) {
            #pragma unroll
            for (int ls = 0; ls < G; ++ls)
                L1STEP(base + ls, ls)
            if (isL1) { pS1 += G * STEP1; pM1 += G * STEP1; }
        }
        if (isS) {
            const int wb = base ^ G;
            #pragma unroll
            for (int i = 0; i < 13; ++i)
                if (i < hs)
                    xsh[wb + soff + i][su] = xn[i];
            if (tpre < T_STEPS) {
                #pragma unroll
                for (int i = 0; i < 13; ++i)
                    if (i < hs)
                        xn[i] = xq[(size_t)i * stepx];
                xq += (size_t)G * stepx;
            }
        }
        tpre += G;
        if (r != 0 && isL2) {
            const int rb = base ^ G;
            #pragma unroll
            for (int ks = 0; ks < G; ++ks)
                L2STEP(rb + ks, ks)
            pS2 += G * STEP2; pM2 += G * STEP2;
        }
        __syncthreads();
        base ^= G;
    }

    // epilogue: L2 consumes the last round (r = NROUND-1, at half base^G;
    // after an even number of flips base == 0, last L1 half was G).
    if (isL2) {
        const int rb = base ^ G;
        #pragma unroll
        for (int ks = 0; ks < G; ++ks)
            L2STEP(rb + ks, ks)
    }

#undef L1STEP
#undef L2STEP
}

extern "C" void kernel_launch(void* const* d_in, const int* in_sizes, int n_in,
                              void* d_out, int out_size)
{
    const float* x   = (const float*)d_in[0];
    const float* W1  = (const float*)d_in[1];
    const float* V   = (const float*)d_in[2];
    const float* W2  = (const float*)d_in[3];
    const float* b1  = (const float*)d_in[4];
    const float* b2  = (const float*)d_in[5];
    const float* th  = (const float*)d_in[6];
    float* out = (float*)d_out;

    dim3 grid(BATCH / NB);   // 512 blocks; 4 blocks/SM -> single wave
    dim3 block(NTHREADS);
    snn_scan_kernel<<<grid, block>>>(x, W1, V, W2, b1, b2, th, out);
}

// round 17
// speedup vs baseline: 2.3226x; 1.1096x over previous
#include <cuda_runtime.h>

// SimpleSNN: T=500 sequential steps, B=2048, 12 -> 38 (RLeaky) -> 7 (Leaky)
// Outputs flat: spk1[T,B,38], mem1[T,B,38], spk2[T,B,7], mem2[T,B,7]
//
// Round-14 champion structure (G=20 static two-phase, 26 barriers, register
// x staging, ballot-bitmask spk1, imm-offset stores) with ONE change:
// L2 is split across TWO warps (wid5: batches 0-1, wid6: batches 2-3;
// -> SMSP1 and SMSP2 instead of one fat warp on SMSP1), 2 threads per
// (b,k) splitting the 4 accumulator chains (h0: acc0,acc1; h1: acc2,acc3),
// W2 held in registers. Recombination via shfl_xor + add is bit-exact
// (IEEE add commutativity). FP order bit-identical to all passing rounds.

#define T_STEPS  500
#define BATCH    2048
#define NIN      12
#define NL1      38
#define NL2      7
#define NB       4              // batch elements per block
#define NTHREADS 224
#define PROD_T   160            // warps 0-4 run the L1 step body (ballot)
#define L1_T     (NB*NL1)       // 152 real L1 threads
#define L2_BASE  160            // L2 = warps 5,6 (64 lanes, 56 active)
#define X_T      (NB*NIN)       // 48 x floats per step
#define STAGE_T  144            // stager threads (3 groups of 48)
#define G        20             // steps per round (500 = 25 rounds)
#define NSLOT    (2*G)          // ring depth (2 rounds)
#define STEP1    (BATCH*NL1)    // element stride between steps, layer-1 outputs
#define STEP2    (BATCH*NL2)    // element stride between steps, layer-2 outputs

__global__ __launch_bounds__(NTHREADS, 4)
void snn_scan_kernel(const float* __restrict__ x,
                     const float* __restrict__ W1,
                     const float* __restrict__ V,
                     const float* __restrict__ W2,
                     const float* __restrict__ pb1,
                     const float* __restrict__ pb2,
                     const float* __restrict__ pth,
                     float* __restrict__ out)
{
    __shared__ float    xsh[NSLOT][X_T];   // x ring: one slot per step
    __shared__ unsigned sbit[NSLOT][8];    // spike bitmask ring: 5 words/slot

    const int tid  = threadIdx.x;
    const int wid  = tid >> 5;
    const int b0   = blockIdx.x * NB;
    const float thr = *pth;

    const size_t stepx = (size_t)BATCH * NIN;
    const float* xblk  = x + (size_t)b0 * NIN;   // 48 contiguous floats per step

    const bool isP  = (tid < PROD_T);    // runs L1 step body (incl. ballot)
    const bool isL1 = (tid < L1_T);      // real L1 neuron
    const bool isS  = (tid < STAGE_T);   // x stager (also an L1 thread)
    const bool isL2 = (tid >= L2_BASE);  // all 64 lanes of warps 5,6

    // ---- layer 1 per-thread state ----
    const float beta1 = *pb1;
    float w1r[NIN];
    float vj = 0.f, mem1 = 0.f, spk1 = 0.f;
    int xoff = 0;
    float *pS1 = out, *pM1 = out;
    if (isL1) {
        int bl = tid / NL1, j = tid - bl * NL1;
        #pragma unroll
        for (int i = 0; i < NIN; ++i) w1r[i] = W1[j * NIN + i];
        vj   = V[j];
        xoff = bl * NIN;
        size_t o = (size_t)(b0 + bl) * NL1 + j;
        pS1 = out + o;
        pM1 = out + (size_t)T_STEPS * BATCH * NL1 + o;
    } else {
        #pragma unroll
        for (int i = 0; i < NIN; ++i) w1r[i] = 0.f;  // ballast lanes: defined math
    }

    // ---- layer 2 per-thread state (2 threads per (b,k), W2 in regs) ----
    const float beta2 = *pb2;
    float mem2 = 0.f;
    float w2a[10], w2b[10];
    int w0i = 0, offi = 0, h2 = 0;
    bool wr2 = false;
    float *pS2 = out, *pM2 = out;
    if (isL2) {
        int t2 = tid - L2_BASE;            // 0..63
        int lw = t2 >> 5;                  // warp-local group: batches {0,1} or {2,3}
        int l  = t2 & 31;
        int p  = l >> 1;                   // pair id 0..15
        wr2    = ((l & 1) == 0) && (p < 14);
        if (p > 13) p = 13;                // clamp idle lanes (keeps shfl pairs sane)
        h2 = l & 1;                        // half: 0 -> acc0,acc1 ; 1 -> acc2,acc3
        int bb = (p >= 7) ? 1 : 0;
        int k  = p - 7 * bb;
        int bl = lw * 2 + bb;
        int base = bl * NL1;               // bit index of (bl, j=0)
        w0i  = base >> 5;
        offi = base & 31;
        #pragma unroll
        for (int q = 0; q < 10; ++q) {
            int ja = 4 * q + 2 * h2;       // element of acc_{2h}
            int jb = ja + 1;               // element of acc_{2h+1}
            w2a[q] = (ja < NL1) ? W2[k * NL1 + ja] : 0.0f;
            w2b[q] = (jb < NL1) ? W2[k * NL1 + jb] : 0.0f;
        }
        size_t o = (size_t)(b0 + bl) * NL2 + k;
        pS2 = out + (size_t)2 * T_STEPS * BATCH * NL1 + o;
        pM2 = pS2 + (size_t)T_STEPS * BATCH * NL2;
    } else {
        #pragma unroll
        for (int q = 0; q < 10; ++q) { w2a[q] = 0.f; w2b[q] = 0.f; }
    }

    // ---- x staging: 144 stagers, 3 groups of 48; group sg owns in-round
    // steps soff..soff+hs-1 for its element su. hs = 7/7/6. ----
    const int su   = tid % 48;
    const int sg   = tid / 48;             // 0,1,2 for tid < 144
    const int hs   = (sg == 2) ? 6 : 7;
    const int soff = 7 * sg;
    float xn[7];
    #pragma unroll
    for (int i = 0; i < 7; ++i) xn[i] = 0.f;
    const float* xq = x;
    int tpre = 2 * G;
    if (isS) {
        // stage round 0 (steps 0..19) directly into slots
        #pragma unroll
        for (int i = 0; i < 7; ++i)
            if (i < hs)
                xsh[soff + i][su] = xblk[su + (size_t)(soff + i) * stepx];
        // hold round 1 (steps 20..39) in regs
        #pragma unroll
        for (int i = 0; i < 7; ++i)
            if (i < hs)
                xn[i] = xblk[su + (size_t)(G + soff + i) * stepx];
        xq = xblk + su + (size_t)(2 * G + soff) * stepx;
    }
    __syncthreads();

    // one L1 step from ring slot SLOT, in-round step index S (0..G-1).
    // Serial fmaf chain — EXACT passing order. Imm-offset stores.
#define L1STEP(SLOT, S)                                                        \
        {                                                                      \
            const float4* xv_ = (const float4*)&xsh[SLOT][xoff];               \
            float4 a = xv_[0], b = xv_[1], c = xv_[2];                         \
            float cur = a.x * w1r[0];                                          \
            cur = fmaf(a.y, w1r[1], cur);                                      \
            cur = fmaf(a.z, w1r[2], cur);                                      \
            cur = fmaf(a.w, w1r[3], cur);                                      \
            cur = fmaf(b.x, w1r[4], cur);                                      \
            cur = fmaf(b.y, w1r[5], cur);                                      \
            cur = fmaf(b.z, w1r[6], cur);                                      \
            cur = fmaf(b.w, w1r[7], cur);                                      \
            cur = fmaf(c.x, w1r[8], cur);                                      \
            cur = fmaf(c.y, w1r[9], cur);                                      \
            cur = fmaf(c.z, w1r[10], cur);                                     \
            cur = fmaf(c.w, w1r[11], cur);                                     \
            float mv_ = fmaf(beta1, mem1, cur);                                \
            mv_ = fmaf(vj, spk1, mv_);                                         \
            bool pr_ = (mv_ > thr);                                            \
            float spv_ = pr_ ? 1.0f : 0.0f;                                    \
            mv_ = fmaf(-spv_, thr, mv_);                                       \
            mem1 = mv_; spk1 = spv_;                                           \
            unsigned bb_ = __ballot_sync(0xFFFFFFFFu, isL1 && pr_);            \
            if ((tid & 31) == 0) sbit[SLOT][wid] = bb_;                        \
            if (isL1) {                                                        \
                pS1[(S) * STEP1] = spv_;                                       \
                pM1[(S) * STEP1] = mv_;                                        \
            }                                                                  \
        }

    // one L2 step (half-thread): this thread runs the acc_{2h} and acc_{2h+1}
    // chains exactly as the champion's 4-acc loop; partner supplies the other
    // partial; cur2 = own + partner (bit-exact by add commutativity).
#define L2STEP(SLOT, S)                                                        \
        {                                                                      \
            unsigned lo_ = sbit[SLOT][w0i];                                    \
            unsigned hi_ = sbit[SLOT][w0i + 1];                                \
            unsigned long long vb_ =                                           \
                ((((unsigned long long)hi_) << 32) | lo_) >> offi;             \
            vb_ &= 0x3FFFFFFFFFull;          /* keep bits 0..37 */             \
            vb_ >>= (unsigned)(2 * h2);      /* align this half's elements */  \
            float accA = 0.0f, accB = 0.0f;                                    \
            _Pragma("unroll")                                                  \
            for (int q = 0; q < 10; ++q) {                                     \
                accA = ((vb_ >> (4 * q + 0)) & 1) ? accA + w2a[q] : accA;      \
                accB = ((vb_ >> (4 * q + 1)) & 1) ? accB + w2b[q] : accB;      \
            }                                                                  \
            float po_ = accA + accB;                                           \
            float pp_ = __shfl_xor_sync(0xFFFFFFFFu, po_, 1);                  \
            float cur2 = po_ + pp_;                                            \
            float m2_ = fmaf(beta2, mem2, cur2);                               \
            float s2_ = (m2_ > thr) ? 1.0f : 0.0f;                             \
            m2_ = fmaf(-s2_, thr, m2_);                                        \
            mem2 = m2_;                                                        \
            if (wr2) {                                                         \
                pS2[(S) * STEP2] = s2_;                                        \
                pM2[(S) * STEP2] = m2_;                                        \
            }                                                                  \
        }

    // L1 round at ring half BASE (0 or G): run G L1 steps; stagers write
    // held regs to the other half and prefetch the round after.
#define L1ROUND(BASE)                                                          \
        if (isP) {                                                             \
            _Pragma("unroll")                                                  \
            for (int ls = 0; ls < G; ++ls)                                     \
                L1STEP((BASE) + ls, ls)                                        \
            if (isL1) { pS1 += G * STEP1; pM1 += G * STEP1; }                  \
        }                                                                      \
        if (isS) {                                                             \
            _Pragma("unroll")                                                  \
            for (int i = 0; i < 7; ++i)                                        \
                if (i < hs)                                                    \
                    xsh[((BASE) ^ G) + soff + i][su] = xn[i];                  \
            if (tpre < T_STEPS) {                                              \
                _Pragma("unroll")                                              \
                for (int i = 0; i < 7; ++i)                                    \
                    if (i < hs)                                                \
                        xn[i] = xq[(size_t)i * stepx];                         \
                xq += (size_t)G * stepx;                                       \
            }                                                                  \
        }                                                                      \
        tpre += G;

#define L2ROUND(BASE)                                                          \
        if (isL2) {                                                            \
            _Pragma("unroll")                                                  \
            for (int ks = 0; ks < G; ++ks)                                     \
                L2STEP((BASE) + ks, ks)                                        \
            pS2 += G * STEP2; pM2 += G * STEP2;                                \
        }

    // round 0: L1 only (steps 0-19; stages 20-39; prefetches 40-59)
    L1ROUND(0)
    __syncthreads();

    // rounds 1..24: L1 leads, L2 trails one round (12 pairs)
    #pragma unroll 1
    for (int r = 0; r < 12; ++r) {
        L1ROUND(G) L2ROUND(0)
        __syncthreads();
        L1ROUND(0) L2ROUND(G)
        __syncthreads();
    }

    // epilogue: L2 for steps 480-499 (half 0)
    L2ROUND(0)

#undef L1STEP
#undef L2STEP
#undef L1ROUND
#undef L2ROUND
}

extern "C" void kernel_launch(void* const* d_in, const int* in_sizes, int n_in,
                              void* d_out, int out_size)
{
    const float* x   = (const float*)d_in[0];
    const float* W1  = (const float*)d_in[1];
    const float* V   = (const float*)d_in[2];
    const float* W2  = (const float*)d_in[3];
    const float* b1  = (const float*)d_in[4];
    const float* b2  = (const float*)d_in[5];
    const float* th  = (const float*)d_in[6];
    float* out = (float*)d_out;

    dim3 grid(BATCH / NB);   // 512 blocks; 4 blocks/SM -> single wave
    dim3 block(NTHREADS);
    snn_scan_kernel<<<grid, block>>>(x, W1, V, W2, b1, b2, th, out);
}